// round 1
// baseline (speedup 1.0000x reference)
#include <cuda_runtime.h>
#include <cuda_bf16.h>
#include <math.h>

#define T 2048
#define H 1024
#define F 2816
#define E 8

#define BM 64
#define BN 64
#define BK 32

// ---------------- scratch (__device__ globals: allocation-free rule) --------
__device__ int   g_cnt[E];
__device__ int   g_tok[E * T];
__device__ float g_wt [E * T];
// H activations, per-expert padded layout: row (e*T + slot), tf32-rounded fp32.
__device__ float g_h[(size_t)E * T * F];   // 8*2048*2816 floats = 184.5 MB

// ---------------- helpers ---------------------------------------------------
__device__ __forceinline__ unsigned f2tf(float v) {
    unsigned r;
    asm("cvt.rna.tf32.f32 %0, %1;" : "=r"(r) : "f"(v));
    return r;
}
__device__ __forceinline__ float f2tf_f(float v) { return __uint_as_float(f2tf(v)); }

__device__ __forceinline__ void mma_tf32(float d[4], const unsigned a[4],
                                         const unsigned b[2]) {
    asm volatile(
        "mma.sync.aligned.m16n8k8.row.col.f32.tf32.tf32.f32 "
        "{%0,%1,%2,%3}, {%4,%5,%6,%7}, {%8,%9}, {%0,%1,%2,%3};\n"
        : "+f"(d[0]), "+f"(d[1]), "+f"(d[2]), "+f"(d[3])
        : "r"(a[0]), "r"(a[1]), "r"(a[2]), "r"(a[3]),
          "r"(b[0]), "r"(b[1]));
}

// ---------------- kernel 0: init (zero output + counters) -------------------
__global__ void k_init(float* out) {
    int n = T * H;
    for (int i = blockIdx.x * blockDim.x + threadIdx.x; i < n;
         i += gridDim.x * blockDim.x)
        out[i] = 0.0f;
    if (blockIdx.x == 0 && threadIdx.x < E) g_cnt[threadIdx.x] = 0;
}

// ---------------- kernel 1: router (one warp per token) ---------------------
__global__ void k_router(const float* __restrict__ x,
                         const float* __restrict__ gw) {
    int warp = (blockIdx.x * blockDim.x + threadIdx.x) >> 5;
    int lane = threadIdx.x & 31;
    if (warp >= T) return;
    const float* xr = x + (size_t)warp * H;
    float logit[E];
#pragma unroll
    for (int e = 0; e < E; e++) {
        const float* g = gw + (size_t)e * H;
        float p = 0.0f;
        for (int k = lane; k < H; k += 32) p += xr[k] * g[k];
#pragma unroll
        for (int o = 16; o; o >>= 1) p += __shfl_xor_sync(0xffffffffu, p, o);
        logit[e] = p;
    }
    if (lane == 0) {
        int i0 = 0; float v0 = logit[0];
#pragma unroll
        for (int e = 1; e < E; e++)
            if (logit[e] > v0) { v0 = logit[e]; i0 = e; }     // strict >: lowest idx on tie
        int i1 = -1; float v1 = -3.0e38f;
#pragma unroll
        for (int e = 0; e < E; e++)
            if (e != i0 && logit[e] > v1) { v1 = logit[e]; i1 = e; }
        float w0 = 1.0f / (1.0f + expf(v1 - v0));   // softmax over [v0,v1]
        float w1 = 1.0f - w0;
        int p0 = atomicAdd(&g_cnt[i0], 1);
        g_tok[i0 * T + p0] = warp; g_wt[i0 * T + p0] = w0;
        int p1 = atomicAdd(&g_cnt[i1], 1);
        g_tok[i1 * T + p1] = warp; g_wt[i1 * T + p1] = w1;
    }
}

// ---------------- kernel 2: GEMM1 (x@w1^T, x@w3^T) + SwiGLU -> g_h ----------
// grid (F/BN, T/BM, E), block 128
__global__ __launch_bounds__(128)
void k_gemm1(const float* __restrict__ x,
             const float* __restrict__ w1,
             const float* __restrict__ w3) {
    int e = blockIdx.z;
    int cnt = g_cnt[e];
    int m0 = blockIdx.y * BM;
    if (m0 >= cnt) return;
    int n0 = blockIdx.x * BN;

    __shared__ float As [BM][36];
    __shared__ float B1s[BN][36];
    __shared__ float B2s[BN][36];
    __shared__ int   toks[BM];

    int tid  = threadIdx.x;
    int wid  = tid >> 5, lane = tid & 31;
    int wm   = (wid >> 1) * 32, wn = (wid & 1) * 32;
    int lr   = lane >> 2, lc = lane & 3;

    if (tid < BM) {
        int r = m0 + tid;
        toks[tid] = g_tok[e * T + min(r, cnt - 1)];
    }

    float accG[2][4][4];
    float accU[2][4][4];
#pragma unroll
    for (int i = 0; i < 2; i++)
#pragma unroll
        for (int j = 0; j < 4; j++)
#pragma unroll
            for (int r = 0; r < 4; r++) { accG[i][j][r] = 0.f; accU[i][j][r] = 0.f; }

    const float* w1e = w1 + (size_t)e * F * H;
    const float* w3e = w3 + (size_t)e * F * H;

    for (int k0 = 0; k0 < H; k0 += BK) {
        __syncthreads();
        // A tile (gathered token rows), with tf32 rounding
#pragma unroll
        for (int q = 0; q < 4; q++) {
            int f = tid + q * 128;
            int r = f >> 3, c4 = (f & 7) * 4;
            float4 v = *(const float4*)(x + (size_t)toks[r] * H + k0 + c4);
            As[r][c4 + 0] = f2tf_f(v.x); As[r][c4 + 1] = f2tf_f(v.y);
            As[r][c4 + 2] = f2tf_f(v.z); As[r][c4 + 3] = f2tf_f(v.w);
        }
        // B tiles (w1, w3): row n (ffn), col k
#pragma unroll
        for (int q = 0; q < 4; q++) {
            int f = tid + q * 128;
            int r = f >> 3, c4 = (f & 7) * 4;
            float4 v = *(const float4*)(w1e + (size_t)(n0 + r) * H + k0 + c4);
            B1s[r][c4 + 0] = f2tf_f(v.x); B1s[r][c4 + 1] = f2tf_f(v.y);
            B1s[r][c4 + 2] = f2tf_f(v.z); B1s[r][c4 + 3] = f2tf_f(v.w);
            float4 u = *(const float4*)(w3e + (size_t)(n0 + r) * H + k0 + c4);
            B2s[r][c4 + 0] = f2tf_f(u.x); B2s[r][c4 + 1] = f2tf_f(u.y);
            B2s[r][c4 + 2] = f2tf_f(u.z); B2s[r][c4 + 3] = f2tf_f(u.w);
        }
        __syncthreads();

#pragma unroll
        for (int kk = 0; kk < BK; kk += 8) {
            unsigned a[2][4];
#pragma unroll
            for (int i = 0; i < 2; i++) {
                int r = wm + i * 16 + lr;
                a[i][0] = __float_as_uint(As[r    ][kk + lc]);
                a[i][1] = __float_as_uint(As[r + 8][kk + lc]);
                a[i][2] = __float_as_uint(As[r    ][kk + lc + 4]);
                a[i][3] = __float_as_uint(As[r + 8][kk + lc + 4]);
            }
#pragma unroll
            for (int j = 0; j < 4; j++) {
                int n = wn + j * 8 + lr;
                unsigned b1[2], b2[2];
                b1[0] = __float_as_uint(B1s[n][kk + lc]);
                b1[1] = __float_as_uint(B1s[n][kk + lc + 4]);
                b2[0] = __float_as_uint(B2s[n][kk + lc]);
                b2[1] = __float_as_uint(B2s[n][kk + lc + 4]);
#pragma unroll
                for (int i = 0; i < 2; i++) {
                    mma_tf32(accG[i][j], a[i], b1);
                    mma_tf32(accU[i][j], a[i], b2);
                }
            }
        }
    }

    // epilogue: h = silu(g)*u, tf32-round, store to padded scratch
#pragma unroll
    for (int i = 0; i < 2; i++) {
#pragma unroll
        for (int p = 0; p < 2; p++) {
            int rr = wm + i * 16 + lr + p * 8;
            size_t row = (size_t)(e * T + m0 + rr);
#pragma unroll
            for (int j = 0; j < 4; j++) {
                float g0 = accG[i][j][p * 2 + 0], g1 = accG[i][j][p * 2 + 1];
                float u0 = accU[i][j][p * 2 + 0], u1 = accU[i][j][p * 2 + 1];
                float h0 = g0 / (1.0f + __expf(-g0)) * u0;
                float h1 = g1 / (1.0f + __expf(-g1)) * u1;
                float2 st; st.x = f2tf_f(h0); st.y = f2tf_f(h1);
                *(float2*)&g_h[row * F + n0 + wn + j * 8 + 2 * lc] = st;
            }
        }
    }
}

// ---------------- kernel 3: GEMM2 (h@w2^T) + weighted scatter ---------------
// grid (H/BN, T/BM, E), block 128
__global__ __launch_bounds__(128)
void k_gemm2(const float* __restrict__ w2, float* __restrict__ out) {
    int e = blockIdx.z;
    int cnt = g_cnt[e];
    int m0 = blockIdx.y * BM;
    if (m0 >= cnt) return;
    int n0 = blockIdx.x * BN;

    __shared__ float As[BM][36];
    __shared__ float Bs[BN][36];

    int tid  = threadIdx.x;
    int wid  = tid >> 5, lane = tid & 31;
    int wm   = (wid >> 1) * 32, wn = (wid & 1) * 32;
    int lr   = lane >> 2, lc = lane & 3;

    float acc[2][4][4];
#pragma unroll
    for (int i = 0; i < 2; i++)
#pragma unroll
        for (int j = 0; j < 4; j++)
#pragma unroll
            for (int r = 0; r < 4; r++) acc[i][j][r] = 0.f;

    const float* w2e = w2 + (size_t)e * H * F;
    const float* hbase = &g_h[(size_t)(e * T + m0) * F];

    for (int k0 = 0; k0 < F; k0 += BK) {
        __syncthreads();
#pragma unroll
        for (int q = 0; q < 4; q++) {
            int f = tid + q * 128;
            int r = f >> 3, c4 = (f & 7) * 4;
            float4 v = *(const float4*)(hbase + (size_t)r * F + k0 + c4);  // already tf32
            As[r][c4 + 0] = v.x; As[r][c4 + 1] = v.y;
            As[r][c4 + 2] = v.z; As[r][c4 + 3] = v.w;
        }
#pragma unroll
        for (int q = 0; q < 4; q++) {
            int f = tid + q * 128;
            int r = f >> 3, c4 = (f & 7) * 4;
            float4 v = *(const float4*)(w2e + (size_t)(n0 + r) * F + k0 + c4);
            Bs[r][c4 + 0] = f2tf_f(v.x); Bs[r][c4 + 1] = f2tf_f(v.y);
            Bs[r][c4 + 2] = f2tf_f(v.z); Bs[r][c4 + 3] = f2tf_f(v.w);
        }
        __syncthreads();

#pragma unroll
        for (int kk = 0; kk < BK; kk += 8) {
            unsigned a[2][4];
#pragma unroll
            for (int i = 0; i < 2; i++) {
                int r = wm + i * 16 + lr;
                a[i][0] = __float_as_uint(As[r    ][kk + lc]);
                a[i][1] = __float_as_uint(As[r + 8][kk + lc]);
                a[i][2] = __float_as_uint(As[r    ][kk + lc + 4]);
                a[i][3] = __float_as_uint(As[r + 8][kk + lc + 4]);
            }
#pragma unroll
            for (int j = 0; j < 4; j++) {
                int n = wn + j * 8 + lr;
                unsigned b[2];
                b[0] = __float_as_uint(Bs[n][kk + lc]);
                b[1] = __float_as_uint(Bs[n][kk + lc + 4]);
#pragma unroll
                for (int i = 0; i < 2; i++) mma_tf32(acc[i][j], a[i], b);
            }
        }
    }

    // epilogue: weighted scatter-add into out
#pragma unroll
    for (int i = 0; i < 2; i++) {
#pragma unroll
        for (int p = 0; p < 2; p++) {
            int rr = wm + i * 16 + lr + p * 8;
            int rg = m0 + rr;
            if (rg >= cnt) continue;
            int   tok = g_tok[e * T + rg];
            float w   = g_wt [e * T + rg];
            float* orow = out + (size_t)tok * H;
#pragma unroll
            for (int j = 0; j < 4; j++) {
                int col = n0 + wn + j * 8 + 2 * lc;
                atomicAdd(&orow[col    ], w * acc[i][j][p * 2 + 0]);
                atomicAdd(&orow[col + 1], w * acc[i][j][p * 2 + 1]);
            }
        }
    }
}

// ---------------- launch ----------------------------------------------------
extern "C" void kernel_launch(void* const* d_in, const int* in_sizes, int n_in,
                              void* d_out, int out_size) {
    const float* x    = (const float*)d_in[0];   // [T, H]
    const float* gw   = (const float*)d_in[1];   // [E, H]
    const float* w1   = (const float*)d_in[2];   // [E, F, H]
    const float* w3   = (const float*)d_in[3];   // [E, F, H]
    const float* w2   = (const float*)d_in[4];   // [E, H, F]
    float* out = (float*)d_out;                  // [T, H]

    k_init<<<512, 256>>>(out);
    k_router<<<T / 8, 256>>>(x, gw);
    dim3 g1(F / BN, T / BM, E);
    k_gemm1<<<g1, 128>>>(x, w1, w3);
    dim3 g2(H / BN, T / BM, E);
    k_gemm2<<<g2, 128>>>(w2, out);
}